// round 1
// baseline (speedup 1.0000x reference)
#include <cuda_runtime.h>
#include <math.h>

// ---------------------------------------------------------------------------
// Problem constants (from reference): N=100000 nodes, E=1600000 edges, D=64.
// Inputs (metadata order):
//  0 node_features [N,64] f32
//  1 node_operations [N,4] f32
//  2 edge_index [2,E] i32
//  3 W1 [128,128]  4 b1[128]  5 W2[128,64]  6 b2[64]
//  7 W3 [64,67]    8 b3[67]   9 P1[64,32]  10 pb1[32]  11 P2[32,1] 12 pb2[1]
// Output: [N,68] f32 = concat(pos(3), feats(64), prob(1)) * mask
// ---------------------------------------------------------------------------

#define NMAX 100000

// Scratch (device globals: allocation-free rule)
__device__ float4 g_nsum4[NMAX * 16];   // [N][64] as float4[N][16]
__device__ float  g_deg[NMAX];

// ---------------------------------------------------------------------------
__global__ void zero_kernel(int n) {
    int stride = gridDim.x * blockDim.x;
    int i = blockIdx.x * blockDim.x + threadIdx.x;
    int tot4 = n * 16;
    float4 z = make_float4(0.f, 0.f, 0.f, 0.f);
    for (int idx = i; idx < tot4; idx += stride) g_nsum4[idx] = z;
    for (int idx = i; idx < n;    idx += stride) g_deg[idx] = 0.f;
}

// ---------------------------------------------------------------------------
// One warp per edge. Lanes 0-15 handle (src += feat[dst]); lanes 16-31 handle
// (dst += feat[src]). Each lane moves one float4 (16B): 16 lanes x 16B = full
// 64-float row, coalesced. Vector RED (v4.f32) quarters atomic op count.
__global__ __launch_bounds__(256) void scatter_kernel(
    const float* __restrict__ nf, const int* __restrict__ ei, int E)
{
    int gw = (blockIdx.x * 256 + threadIdx.x) >> 5;
    int lane = threadIdx.x & 31;
    if (gw >= E) return;
    int src = __ldg(ei + gw);
    int dst = __ldg(ei + E + gw);
    if (lane == 0)       atomicAdd(&g_deg[src], 1.f);
    else if (lane == 16) atomicAdd(&g_deg[dst], 1.f);
    int node  = (lane < 16) ? src : dst;
    int other = (lane < 16) ? dst : src;
    int c = lane & 15;
    float4 v = __ldg((const float4*)nf + (size_t)other * 16 + c);
    float* p = (float*)(g_nsum4 + (size_t)node * 16 + c);
    asm volatile("red.global.add.v4.f32 [%0], {%1,%2,%3,%4};"
                 :: "l"(p), "f"(v.x), "f"(v.y), "f"(v.z), "f"(v.w)
                 : "memory");
}

// ---------------------------------------------------------------------------
// Fused MLP. All weights live in dynamic smem; 8 warps/block, 4 rows/warp.
// Shared layout (floats):
#define OFF_W1   0        // 16384
#define OFF_B1   16384    // 128
#define OFF_W2   16512    // 8192
#define OFF_B2   24704    // 64
#define OFF_W3   24768    // 4288   (row stride 67)
#define OFF_B3   29056    // 67 (pad to 68)
#define OFF_P1   29124    // 2048
#define OFF_PB1  31172    // 32
#define OFF_P2   31204    // 32
#define OFF_PB2  31236    // 1 (pad to 4)
#define PWBASE   31240
// per-warp scratch: ctx[4][128] | h1[4][128] | h2[4][64] | feats[4][64] |
//                   pos[4][4] | mask[4]   => 4*388 + 4 = 1556, pad 1560
#define PW       1560
#define SMEM_FLOATS (PWBASE + 8 * PW)   // 43720 floats = 174880 B

__global__ __launch_bounds__(256, 1) void mlp_kernel(
    const float* __restrict__ nf, const float* __restrict__ ops,
    const float* __restrict__ W1, const float* __restrict__ b1,
    const float* __restrict__ W2, const float* __restrict__ b2,
    const float* __restrict__ W3, const float* __restrict__ b3,
    const float* __restrict__ P1, const float* __restrict__ pb1,
    const float* __restrict__ P2, const float* __restrict__ pb2,
    float* __restrict__ out, int n)
{
    extern __shared__ float sm[];
    int tid = threadIdx.x;
    int warp = tid >> 5;
    int lane = tid & 31;

    // ---- cooperative weight load ----
    {
        for (int i = tid; i < 16384; i += 256) sm[OFF_W1 + i] = W1[i];
        for (int i = tid; i < 128;   i += 256) sm[OFF_B1 + i] = b1[i];
        for (int i = tid; i < 8192;  i += 256) sm[OFF_W2 + i] = W2[i];
        for (int i = tid; i < 64;    i += 256) sm[OFF_B2 + i] = b2[i];
        for (int i = tid; i < 4288;  i += 256) sm[OFF_W3 + i] = W3[i];
        for (int i = tid; i < 67;    i += 256) sm[OFF_B3 + i] = b3[i];
        for (int i = tid; i < 2048;  i += 256) sm[OFF_P1 + i] = P1[i];
        for (int i = tid; i < 32;    i += 256) sm[OFF_PB1 + i] = pb1[i];
        for (int i = tid; i < 32;    i += 256) sm[OFF_P2 + i] = P2[i];
        if (tid == 0) sm[OFF_PB2] = pb2[0];
    }
    __syncthreads();

    float* sctx = sm + PWBASE + warp * PW;   // [4][128]
    float* sh1  = sctx + 512;                // [4][128]
    float* sh2  = sh1 + 512;                 // [4][64]
    float* sft  = sh2 + 256;                 // [4][64]
    float* spos = sft + 256;                 // [4][4]
    float* smk  = spos + 16;                 // [4]

    for (int base = blockIdx.x * 32; base < n; base += gridDim.x * 32) {
        int row0 = base + warp * 4;

        // ---- phase 0: build ctx = [nf, nsum/max(deg,1)], mask ----
        #pragma unroll
        for (int r = 0; r < 4; r++) {
            int row = min(row0 + r, n - 1);
            float dg = g_deg[row];
            float invd = 1.f / fmaxf(dg, 1.f);
            for (int idx = lane; idx < 64; idx += 32) {
                sctx[r * 128 + idx]      = nf[(size_t)row * 64 + idx];
                sctx[r * 128 + 64 + idx] =
                    ((const float*)g_nsum4)[(size_t)row * 64 + idx] * invd;
            }
            if (lane == 0) {
                const float* o = ops + (size_t)row * 4;
                float o0 = o[0], o1 = o[1], o2 = o[2], o3 = o[3];
                float m = fmaxf(fmaxf(o0, o1), fmaxf(o2, o3));
                float e0 = expf(o0 - m);
                float s = e0 + expf(o1 - m) + expf(o2 - m) + expf(o3 - m);
                float p0 = e0 / s;
                smk[r] = (p0 > 0.5f && dg > 0.f) ? 1.f : 0.f;
            }
        }
        __syncwarp();

        // ---- phase 1: h1 = relu(ctx @ W1 + b1), 128 out ----
        {
            float a[4][4];
            #pragma unroll
            for (int i = 0; i < 4; i++) {
                float bv = sm[OFF_B1 + lane + 32 * i];
                #pragma unroll
                for (int r = 0; r < 4; r++) a[i][r] = bv;
            }
            #pragma unroll 4
            for (int k = 0; k < 128; k++) {
                float c0 = sctx[k], c1 = sctx[128 + k];
                float c2 = sctx[256 + k], c3 = sctx[384 + k];
                #pragma unroll
                for (int i = 0; i < 4; i++) {
                    float w = sm[OFF_W1 + k * 128 + lane + 32 * i];
                    a[i][0] += w * c0; a[i][1] += w * c1;
                    a[i][2] += w * c2; a[i][3] += w * c3;
                }
            }
            #pragma unroll
            for (int i = 0; i < 4; i++)
                #pragma unroll
                for (int r = 0; r < 4; r++)
                    sh1[r * 128 + lane + 32 * i] = fmaxf(a[i][r], 0.f);
        }
        __syncwarp();

        // ---- phase 2: h2 = relu(h1 @ W2 + b2), 64 out ----
        {
            float a[2][4];
            #pragma unroll
            for (int i = 0; i < 2; i++) {
                float bv = sm[OFF_B2 + lane + 32 * i];
                #pragma unroll
                for (int r = 0; r < 4; r++) a[i][r] = bv;
            }
            #pragma unroll 4
            for (int k = 0; k < 128; k++) {
                float c0 = sh1[k], c1 = sh1[128 + k];
                float c2 = sh1[256 + k], c3 = sh1[384 + k];
                #pragma unroll
                for (int i = 0; i < 2; i++) {
                    float w = sm[OFF_W2 + k * 64 + lane + 32 * i];
                    a[i][0] += w * c0; a[i][1] += w * c1;
                    a[i][2] += w * c2; a[i][3] += w * c3;
                }
            }
            #pragma unroll
            for (int i = 0; i < 2; i++)
                #pragma unroll
                for (int r = 0; r < 4; r++)
                    sh2[r * 64 + lane + 32 * i] = fmaxf(a[i][r], 0.f);
        }
        __syncwarp();

        // ---- phase 3: gen = h2 @ W3 + b3, 67 out (pos 0..2, feats 3..66) ----
        {
            float a[3][4];
            bool v2 = (lane < 3);
            #pragma unroll
            for (int i = 0; i < 3; i++) {
                int j = lane + 32 * i;
                float bv = (i < 2 || v2) ? sm[OFF_B3 + j] : 0.f;
                #pragma unroll
                for (int r = 0; r < 4; r++) a[i][r] = bv;
            }
            #pragma unroll 4
            for (int k = 0; k < 64; k++) {
                float c0 = sh2[k], c1 = sh2[64 + k];
                float c2 = sh2[128 + k], c3 = sh2[192 + k];
                float w0 = sm[OFF_W3 + k * 67 + lane];
                float w1 = sm[OFF_W3 + k * 67 + lane + 32];
                float w2 = v2 ? sm[OFF_W3 + k * 67 + lane + 64] : 0.f;
                a[0][0] += w0 * c0; a[0][1] += w0 * c1; a[0][2] += w0 * c2; a[0][3] += w0 * c3;
                a[1][0] += w1 * c0; a[1][1] += w1 * c1; a[1][2] += w1 * c2; a[1][3] += w1 * c3;
                a[2][0] += w2 * c0; a[2][1] += w2 * c1; a[2][2] += w2 * c2; a[2][3] += w2 * c3;
            }
            #pragma unroll
            for (int r = 0; r < 4; r++) {
                if (lane < 3) { spos[r * 4 + lane] = a[0][r]; }
                else          { sft[r * 64 + lane - 3] = a[0][r]; }
                sft[r * 64 + lane + 29] = a[1][r];     // j = lane+32 -> feat idx lane+29
                if (v2) sft[r * 64 + lane + 61] = a[2][r];  // j = lane+64 -> feat idx lane+61
            }
        }
        __syncwarp();

        // ---- phase 4/5: p = relu(feats @ P1 + pb1); prob = sigmoid(p @ P2 + pb2) ----
        float prob[4];
        {
            float a[4];
            float bv = sm[OFF_PB1 + lane];
            #pragma unroll
            for (int r = 0; r < 4; r++) a[r] = bv;
            #pragma unroll 4
            for (int k = 0; k < 64; k++) {
                float w = sm[OFF_P1 + k * 32 + lane];
                a[0] += w * sft[k];       a[1] += w * sft[64 + k];
                a[2] += w * sft[128 + k]; a[3] += w * sft[192 + k];
            }
            float p2 = sm[OFF_P2 + lane];
            float pb2v = sm[OFF_PB2];
            #pragma unroll
            for (int r = 0; r < 4; r++) {
                float part = fmaxf(a[r], 0.f) * p2;
                #pragma unroll
                for (int off = 16; off > 0; off >>= 1)
                    part += __shfl_xor_sync(0xffffffffu, part, off);
                prob[r] = 1.f / (1.f + expf(-(part + pb2v)));
            }
        }

        // ---- phase 6: masked store of [pos(3), feats(64), prob(1)] ----
        #pragma unroll
        for (int r = 0; r < 4; r++) {
            int row = row0 + r;
            if (row >= n) continue;
            float mk = smk[r];
            for (int idx = lane; idx < 68; idx += 32) {
                float v;
                if (idx < 3)       v = spos[r * 4 + idx];
                else if (idx < 67) v = sft[r * 64 + idx - 3];
                else               v = prob[r];
                out[(size_t)row * 68 + idx] = v * mk;
            }
        }
        __syncwarp();
    }
}

// ---------------------------------------------------------------------------
extern "C" void kernel_launch(void* const* d_in, const int* in_sizes, int n_in,
                              void* d_out, int out_size)
{
    const float* nf  = (const float*)d_in[0];
    const float* ops = (const float*)d_in[1];
    const int*   ei  = (const int*)d_in[2];
    const float* W1  = (const float*)d_in[3];
    const float* b1  = (const float*)d_in[4];
    const float* W2  = (const float*)d_in[5];
    const float* b2  = (const float*)d_in[6];
    const float* W3  = (const float*)d_in[7];
    const float* b3  = (const float*)d_in[8];
    const float* P1  = (const float*)d_in[9];
    const float* pb1 = (const float*)d_in[10];
    const float* P2  = (const float*)d_in[11];
    const float* pb2 = (const float*)d_in[12];
    float* out = (float*)d_out;

    int n = in_sizes[0] / 64;
    int E = in_sizes[2] / 2;

    // 1) zero scratch
    zero_kernel<<<2048, 256>>>(n);

    // 2) edge scatter (one warp per edge)
    int nwarps = E;
    int blocks = (nwarps * 32 + 255) / 256;
    scatter_kernel<<<blocks, 256>>>(nf, ei, E);

    // 3) fused MLP
    size_t smem = SMEM_FLOATS * sizeof(float);
    cudaFuncSetAttribute(mlp_kernel, cudaFuncAttributeMaxDynamicSharedMemorySize,
                         (int)smem);
    mlp_kernel<<<148, 256, smem>>>(nf, ops, W1, b1, W2, b2, W3, b3,
                                   P1, pb1, P2, pb2, out, n);
}

// round 2
// speedup vs baseline: 1.5154x; 1.5154x over previous
#include <cuda_runtime.h>
#include <math.h>

// ---------------------------------------------------------------------------
// N=100000 nodes, E=1600000 edges, D=64.
// Inputs: 0 nf[N,64] 1 ops[N,4] 2 edge_index[2,E] i32
//  3 W1[128,128] 4 b1[128] 5 W2[128,64] 6 b2[64] 7 W3[64,67] 8 b3[67]
//  9 P1[64,32] 10 pb1[32] 11 P2[32] 12 pb2[1]
// Output: [N,68] = concat(gen[0:67], prob) * mask
// ---------------------------------------------------------------------------

#define NMAX 100000
typedef unsigned long long u64;

__device__ float4 g_nsum4[NMAX * 16];
__device__ float  g_deg[NMAX];

__device__ __forceinline__ u64 pack2(float lo, float hi) {
    u64 d;
    asm("mov.b64 %0, {%1, %2};" : "=l"(d) : "f"(lo), "f"(hi));
    return d;
}
__device__ __forceinline__ void unpack2(u64 v, float &lo, float &hi) {
    asm("mov.b64 {%0, %1}, %2;" : "=f"(lo), "=f"(hi) : "l"(v));
}
#define FFMA2(d, a, b) \
    asm("fma.rn.f32x2 %0, %1, %2, %0;" : "+l"(d) : "l"(a), "l"(b))

// ---------------------------------------------------------------------------
__global__ void zero_kernel(int n) {
    int stride = gridDim.x * blockDim.x;
    int i = blockIdx.x * blockDim.x + threadIdx.x;
    int tot4 = n * 16;
    float4 z = make_float4(0.f, 0.f, 0.f, 0.f);
    for (int idx = i; idx < tot4; idx += stride) g_nsum4[idx] = z;
    for (int idx = i; idx < n;    idx += stride) g_deg[idx] = 0.f;
}

// ---------------------------------------------------------------------------
// One warp per edge; lanes 0-15: src += nf[dst]; lanes 16-31: dst += nf[src].
__global__ __launch_bounds__(256) void scatter_kernel(
    const float* __restrict__ nf, const int* __restrict__ ei, int E)
{
    int gw = (blockIdx.x * 256 + threadIdx.x) >> 5;
    int lane = threadIdx.x & 31;
    if (gw >= E) return;
    int src = __ldg(ei + gw);
    int dst = __ldg(ei + E + gw);
    if (lane == 0)       atomicAdd(&g_deg[src], 1.f);
    else if (lane == 16) atomicAdd(&g_deg[dst], 1.f);
    int node  = (lane < 16) ? src : dst;
    int other = (lane < 16) ? dst : src;
    int c = lane & 15;
    float4 v = __ldg((const float4*)nf + (size_t)other * 16 + c);
    float* p = (float*)(g_nsum4 + (size_t)node * 16 + c);
    asm volatile("red.global.add.v4.f32 [%0], {%1,%2,%3,%4};"
                 :: "l"(p), "f"(v.x), "f"(v.y), "f"(v.z), "f"(v.w)
                 : "memory");
}

// ---------------------------------------------------------------------------
// Fused MLP with packed f32x2 FMA. Shared layout (float offsets):
#define OFF_W1   0        // 16384
#define OFF_B1   16384    // 128
#define OFF_W2   16512    // 8192
#define OFF_B2   24704    // 64
#define OFF_W3   24768    // 64*68 = 4352 (padded stride 68, col67=0)
#define OFF_B3   29120    // 68 (padded)
#define OFF_P1   29188    // 2048
#define OFF_PB1  31236    // 32
#define OFF_P2   31268    // 32
#define OFF_PB2  31300    // 1 (pad 4)
#define PWBASE   31304
// per-warp: ctxd[4][256] | h1d[4][256] | h2d[4][128] | gen[4][68] | mk[4]
#define PW_CTX   0
#define PW_H1    1024
#define PW_H2    2048
#define PW_GEN   2560
#define PW_MK    2832
#define PW       2840
#define SMEM_FLOATS (PWBASE + 8 * PW)   // 54024 floats = 216096 B

__global__ __launch_bounds__(256, 1) void mlp_kernel(
    const float* __restrict__ nf, const float* __restrict__ ops,
    const float* __restrict__ W1, const float* __restrict__ b1,
    const float* __restrict__ W2, const float* __restrict__ b2,
    const float* __restrict__ W3, const float* __restrict__ b3,
    const float* __restrict__ P1, const float* __restrict__ pb1,
    const float* __restrict__ P2, const float* __restrict__ pb2,
    float* __restrict__ out, int n)
{
    extern __shared__ float sm[];
    int tid = threadIdx.x;
    int warp = tid >> 5;
    int lane = tid & 31;

    // ---- cooperative weight load ----
    for (int i = tid; i < 16384; i += 256) sm[OFF_W1 + i] = W1[i];
    for (int i = tid; i < 128;   i += 256) sm[OFF_B1 + i] = b1[i];
    for (int i = tid; i < 8192;  i += 256) sm[OFF_W2 + i] = W2[i];
    for (int i = tid; i < 64;    i += 256) sm[OFF_B2 + i] = b2[i];
    for (int i = tid; i < 64 * 68; i += 256) {                 // W3 padded
        int r = i / 68, c = i % 68;
        sm[OFF_W3 + i] = (c < 67) ? W3[r * 67 + c] : 0.f;
    }
    for (int i = tid; i < 68;   i += 256) sm[OFF_B3 + i] = (i < 67) ? b3[i] : 0.f;
    for (int i = tid; i < 2048; i += 256) sm[OFF_P1 + i] = P1[i];
    for (int i = tid; i < 32;   i += 256) sm[OFF_PB1 + i] = pb1[i];
    for (int i = tid; i < 32;   i += 256) sm[OFF_P2 + i] = P2[i];
    if (tid == 0) sm[OFF_PB2] = pb2[0];
    __syncthreads();

    float* pw   = sm + PWBASE + warp * PW;
    float* sctx = pw + PW_CTX;   // duplicated ctx  [4][256]
    float* sh1  = pw + PW_H1;    // duplicated h1   [4][256]
    float* sh2  = pw + PW_H2;    // duplicated h2   [4][128]
    float* sgen = pw + PW_GEN;   // gen             [4][68]
    float* smk  = pw + PW_MK;    // mask            [4]

    for (int base = blockIdx.x * 32; base < n; base += gridDim.x * 32) {
        int row0 = base + warp * 4;

        // ---- phase 0: ctx (duplicated) + mask ----
        #pragma unroll
        for (int r = 0; r < 4; r++) {
            int row = min(row0 + r, n - 1);
            float dg = g_deg[row];
            float invd = 1.f / fmaxf(dg, 1.f);
            #pragma unroll
            for (int t = 0; t < 2; t++) {
                int idx = lane + 32 * t;
                float a = nf[(size_t)row * 64 + idx];
                float b = ((const float*)g_nsum4)[(size_t)row * 64 + idx] * invd;
                *(float2*)&sctx[r * 256 + 2 * idx]       = make_float2(a, a);
                *(float2*)&sctx[r * 256 + 128 + 2 * idx] = make_float2(b, b);
            }
            if (lane == 0) {
                const float* o = ops + (size_t)row * 4;
                float o0 = o[0], o1 = o[1], o2 = o[2], o3 = o[3];
                float m = fmaxf(fmaxf(o0, o1), fmaxf(o2, o3));
                float e0 = expf(o0 - m);
                float s = e0 + expf(o1 - m) + expf(o2 - m) + expf(o3 - m);
                smk[r] = ((e0 / s) > 0.5f && dg > 0.f) ? 1.f : 0.f;
            }
        }
        __syncwarp();

        // ---- phase 1: h1 = relu(ctx @ W1 + b1) : 128 out, pairs ----
        {
            u64 acc[2][4];
            #pragma unroll
            for (int i = 0; i < 2; i++) {
                u64 bv = *(const u64*)&sm[OFF_B1 + 2 * lane + 64 * i];
                #pragma unroll
                for (int r = 0; r < 4; r++) acc[i][r] = bv;
            }
            #pragma unroll 4
            for (int k = 0; k < 128; k++) {
                u64 c0 = *(const u64*)&sctx[2 * k];
                u64 c1 = *(const u64*)&sctx[256 + 2 * k];
                u64 c2 = *(const u64*)&sctx[512 + 2 * k];
                u64 c3 = *(const u64*)&sctx[768 + 2 * k];
                u64 w0 = *(const u64*)&sm[OFF_W1 + k * 128 + 2 * lane];
                u64 w1 = *(const u64*)&sm[OFF_W1 + k * 128 + 64 + 2 * lane];
                FFMA2(acc[0][0], w0, c0); FFMA2(acc[0][1], w0, c1);
                FFMA2(acc[0][2], w0, c2); FFMA2(acc[0][3], w0, c3);
                FFMA2(acc[1][0], w1, c0); FFMA2(acc[1][1], w1, c1);
                FFMA2(acc[1][2], w1, c2); FFMA2(acc[1][3], w1, c3);
            }
            #pragma unroll
            for (int i = 0; i < 2; i++)
                #pragma unroll
                for (int r = 0; r < 4; r++) {
                    float lo, hi; unpack2(acc[i][r], lo, hi);
                    lo = fmaxf(lo, 0.f); hi = fmaxf(hi, 0.f);
                    *(float4*)&sh1[r * 256 + 4 * lane + 128 * i] =
                        make_float4(lo, lo, hi, hi);
                }
        }
        __syncwarp();

        // ---- phase 2: h2 = relu(h1 @ W2 + b2) : 64 out, pairs ----
        {
            u64 acc[4];
            u64 bv = *(const u64*)&sm[OFF_B2 + 2 * lane];
            #pragma unroll
            for (int r = 0; r < 4; r++) acc[r] = bv;
            #pragma unroll 4
            for (int k = 0; k < 128; k++) {
                u64 w  = *(const u64*)&sm[OFF_W2 + k * 64 + 2 * lane];
                FFMA2(acc[0], w, *(const u64*)&sh1[2 * k]);
                FFMA2(acc[1], w, *(const u64*)&sh1[256 + 2 * k]);
                FFMA2(acc[2], w, *(const u64*)&sh1[512 + 2 * k]);
                FFMA2(acc[3], w, *(const u64*)&sh1[768 + 2 * k]);
            }
            #pragma unroll
            for (int r = 0; r < 4; r++) {
                float lo, hi; unpack2(acc[r], lo, hi);
                lo = fmaxf(lo, 0.f); hi = fmaxf(hi, 0.f);
                *(float4*)&sh2[r * 128 + 4 * lane] = make_float4(lo, lo, hi, hi);
            }
        }
        __syncwarp();

        // ---- phase 3: gen = h2 @ W3 + b3 : 68 out (pad), pairs ----
        {
            u64 acc[2][4];
            u64 b0 = *(const u64*)&sm[OFF_B3 + 2 * lane];
            u64 b1v = *(const u64*)&sm[OFF_B3 + 64 + 2 * lane]; // valid lane<2
            #pragma unroll
            for (int r = 0; r < 4; r++) { acc[0][r] = b0; acc[1][r] = b1v; }
            #pragma unroll 4
            for (int k = 0; k < 64; k++) {
                u64 c0 = *(const u64*)&sh2[2 * k];
                u64 c1 = *(const u64*)&sh2[128 + 2 * k];
                u64 c2 = *(const u64*)&sh2[256 + 2 * k];
                u64 c3 = *(const u64*)&sh2[384 + 2 * k];
                u64 w0 = *(const u64*)&sm[OFF_W3 + k * 68 + 2 * lane];
                u64 w1 = *(const u64*)&sm[OFF_W3 + k * 68 + 64 + 2 * lane];
                FFMA2(acc[0][0], w0, c0); FFMA2(acc[0][1], w0, c1);
                FFMA2(acc[0][2], w0, c2); FFMA2(acc[0][3], w0, c3);
                FFMA2(acc[1][0], w1, c0); FFMA2(acc[1][1], w1, c1);
                FFMA2(acc[1][2], w1, c2); FFMA2(acc[1][3], w1, c3);
            }
            #pragma unroll
            for (int r = 0; r < 4; r++) {
                *(u64*)&sgen[r * 68 + 2 * lane] = acc[0][r];
                if (lane < 2)
                    *(u64*)&sgen[r * 68 + 64 + 2 * lane] = acc[1][r];
            }
        }
        __syncwarp();

        // ---- phase 4: prob = sigmoid(relu(feats @ P1 + pb1) @ P2 + pb2) ----
        float prob[4];
        {
            float a[4];
            float bv = sm[OFF_PB1 + lane];
            #pragma unroll
            for (int r = 0; r < 4; r++) a[r] = bv;
            #pragma unroll 4
            for (int k = 0; k < 64; k++) {
                float w = sm[OFF_P1 + k * 32 + lane];
                a[0] = fmaf(w, sgen[3 + k],       a[0]);
                a[1] = fmaf(w, sgen[68 + 3 + k],  a[1]);
                a[2] = fmaf(w, sgen[136 + 3 + k], a[2]);
                a[3] = fmaf(w, sgen[204 + 3 + k], a[3]);
            }
            float p2 = sm[OFF_P2 + lane];
            float pb2v = sm[OFF_PB2];
            #pragma unroll
            for (int r = 0; r < 4; r++) {
                float part = fmaxf(a[r], 0.f) * p2;
                #pragma unroll
                for (int off = 16; off > 0; off >>= 1)
                    part += __shfl_xor_sync(0xffffffffu, part, off);
                prob[r] = 1.f / (1.f + expf(-(part + pb2v)));
            }
        }

        // ---- phase 5: masked vectorized store: out = [gen[0:67], prob]*mk --
        #pragma unroll
        for (int r = 0; r < 4; r++) {
            int row = row0 + r;
            if (row >= n || lane >= 17) continue;
            float mk = smk[r];
            float4 v = *(const float4*)&sgen[r * 68 + 4 * lane];
            if (lane == 16) v.w = prob[r];
            v.x *= mk; v.y *= mk; v.z *= mk; v.w *= mk;
            *(float4*)(out + (size_t)row * 68 + 4 * lane) = v;
        }
        __syncwarp();
    }
}

// ---------------------------------------------------------------------------
extern "C" void kernel_launch(void* const* d_in, const int* in_sizes, int n_in,
                              void* d_out, int out_size)
{
    const float* nf  = (const float*)d_in[0];
    const float* ops = (const float*)d_in[1];
    const int*   ei  = (const int*)d_in[2];
    const float* W1  = (const float*)d_in[3];
    const float* b1  = (const float*)d_in[4];
    const float* W2  = (const float*)d_in[5];
    const float* b2  = (const float*)d_in[6];
    const float* W3  = (const float*)d_in[7];
    const float* b3  = (const float*)d_in[8];
    const float* P1  = (const float*)d_in[9];
    const float* pb1 = (const float*)d_in[10];
    const float* P2  = (const float*)d_in[11];
    const float* pb2 = (const float*)d_in[12];
    float* out = (float*)d_out;

    int n = in_sizes[0] / 64;
    int E = in_sizes[2] / 2;

    zero_kernel<<<2048, 256>>>(n);

    int blocks = (E * 32 + 255) / 256;
    scatter_kernel<<<blocks, 256>>>(nf, ei, E);

    size_t smem = SMEM_FLOATS * sizeof(float);
    cudaFuncSetAttribute(mlp_kernel, cudaFuncAttributeMaxDynamicSharedMemorySize,
                         (int)smem);
    mlp_kernel<<<148, 256, smem>>>(nf, ops, W1, b1, W2, b2, W3, b3,
                                   P1, pb1, P2, pb2, out, n);
}